// round 6
// baseline (speedup 1.0000x reference)
#include <cuda_runtime.h>
#include <math.h>

#define Bn 8
#define Hn 256
#define Wn 256
#define R  4
#define TR 2
#define NROWS (TR + 2*R)         // 10 halo rows (fits uint32 mask)
#define GW (Wn + 2*R)            // 264 padded columns (idx = col + R)
#define NBLK (Bn * (Hn / TR))    // 1024 blocks
#define PADV 0x0FFF0FFFu         // "far" in both packed halves

// Per-block partials + completion counter. g_done is statically zero and is
// reset by the last block each launch, so graph replays start clean.
// g_part is fully overwritten every launch. No device allocations anywhere.
__device__ float g_part[NBLK];
__device__ unsigned int g_done = 0;

__device__ __forceinline__ int vdist(unsigned int m, int p)
{
    const unsigned int down = m >> p;
    const unsigned int up   = m << (31 - p);
    const int dd = down ? (__ffs((int)down) - 1) : 63;
    const int du = up   ? __clz((int)up)         : 63;
    return min(dd, du);
}

__global__ void __launch_bounds__(256)
boundary_loss_kernel(const float* __restrict__ pred,
                     const float* __restrict__ targ,
                     float* __restrict__ out)
{
    const int tile = blockIdx.x;             // 0 .. 1023
    const int b    = tile >> 7;              // 128 row-tiles per image
    const int h0   = (tile & 127) * TR;      // first output row of this tile
    const int w    = threadIdx.x;            // column (one per thread)

    __shared__ unsigned int sh[TR][GW];      // packed (d2_to_bg | d2_to_fg<<16)
    __shared__ float lutW[34];
    __shared__ float ws[8];
    __shared__ int   s_last;

    // weight LUT: d2 = 0..32 exact, 33 = far sentinel
    if (w < 34) {
        const float d = (w == 33) ? 64.0f : sqrtf((float)w);
        lutW[w] = 1.0f / (1.0f + __expf((d - 3.0f) * 0.2f));
    }
    // left/right pads (indices 0..3 and 260..263)
    if (w < 2 * R) {
        const int idx = (w < R) ? w : (Wn + w);
        #pragma unroll
        for (int r = 0; r < TR; ++r) sh[r][idx] = PADV;
    }

    // ---- validity mask for halo rows (no per-row branches) ----
    const int start = h0 - R;
    unsigned int vm = (1u << NROWS) - 1u;
    if (start < 0)          vm &= ~((1u << (-start)) - 1u);
    if (start + NROWS > Hn) vm &=  (1u << (Hn - start)) - 1u;

    // ---- per-column class bitmask: targets are exactly 0.0f / 1.0f,
    //      so bit 23 of the float encoding IS the class flag ----
    const unsigned int* timg =
        (const unsigned int*)(targ + b * (Hn * Wn));
    unsigned int fgm = 0u;
    #pragma unroll
    for (int k = 0; k < NROWS; ++k) {
        const int hh = min(max(start + k, 0), Hn - 1);
        const unsigned int u = __ldg(&timg[hh * Wn + w]);
        fgm |= ((u >> 23) & 1u) << k;
    }
    fgm &= vm;
    const unsigned int bgm = ~fgm & vm;

    // ---- vertical pass: packed d2 for both classes ----
    #pragma unroll
    for (int r = 0; r < TR; ++r) {
        const int p  = r + R;
        const int dp = vdist(bgm, p);
        const int dn = vdist(fgm, p);
        sh[r][w + R] = (unsigned)(dp * dp) | ((unsigned)(dn * dn) << 16);
    }
    __syncthreads();

    // ---- horizontal 9-tap packed envelope + fused BCE * LUT weight ----
    const float* pimg = pred + b * (Hn * Wn);
    float acc = 0.0f;

    #pragma unroll
    for (int r = 0; r < TR; ++r) {
        unsigned int best = 0xFFFFFFFFu;
        #pragma unroll
        for (int k = 0; k < 9; ++k) {
            const int kk = k - R;
            const unsigned int add = (unsigned)(kk * kk) * 0x00010001u;
            best = __vminu2(best, sh[r][w + k] + add);
        }

        const bool fg = (fgm >> (r + R)) & 1u;
        const unsigned int d2 = fg ? (best & 0xFFFFu) : (best >> 16);
        const float weight = lutW[min(d2, 33u)];

        const float x   = pimg[(h0 + r) * Wn + w];
        const float bce = fmaxf(x, 0.0f) - (fg ? x : 0.0f)
                        + __logf(1.0f + __expf(-fabsf(x)));
        acc = fmaf(bce, weight, acc);
    }

    // ---- block reduction (8 warps) ----
    #pragma unroll
    for (int off = 16; off > 0; off >>= 1)
        acc += __shfl_xor_sync(0xffffffffu, acc, off);
    if ((w & 31) == 0) ws[w >> 5] = acc;
    __syncthreads();

    // ---- publish per-block partial (contention-free STG), then count ----
    if (w == 0) {
        float s = 0.0f;
        #pragma unroll
        for (int i = 0; i < 8; ++i) s += ws[i];
        g_part[tile] = s;
        __threadfence();
        const unsigned int done = atomicAdd(&g_done, 1u);
        s_last = (done == (unsigned int)(NBLK - 1));
    }
    __syncthreads();

    // ---- last block: reduce all 1024 partials and finalize ----
    if (s_last) {
        __threadfence();                       // acquire partials
        const float4 p = ((const float4*)g_part)[w];   // 256 x float4 = 1024
        float s = (p.x + p.y) + (p.z + p.w);
        #pragma unroll
        for (int off = 16; off > 0; off >>= 1)
            s += __shfl_xor_sync(0xffffffffu, s, off);
        if ((w & 31) == 0) ws[w >> 5] = s;
        __syncthreads();
        if (w == 0) {
            float tot = 0.0f;
            #pragma unroll
            for (int i = 0; i < 8; ++i) tot += ws[i];
            out[0] = tot * (1.0f / (float)(Bn * Hn * Wn));
            g_done = 0u;                       // reset for next launch / replay
        }
    }
}

extern "C" void kernel_launch(void* const* d_in, const int* in_sizes, int n_in,
                              void* d_out, int out_size)
{
    const float* pred = (const float*)d_in[0];
    const float* targ = (const float*)d_in[1];
    float* out = (float*)d_out;

    boundary_loss_kernel<<<NBLK, 256>>>(pred, targ, out);
}

// round 7
// speedup vs baseline: 1.2169x; 1.2169x over previous
#include <cuda_runtime.h>
#include <math.h>

#define Bn 8
#define Hn 256
#define Wn 256
#define R  4
#define TRB 8                     // output rows per block
#define NROWS (TRB + 2*R)         // 16 halo rows (fits uint32 mask)
#define GW (Wn + 2*R)             // 264 padded columns (idx = col + R)
#define NBLK (Bn * (Hn / TRB))    // 256 blocks
#define PADV 0x0FFF0FFFu          // "far" in both packed halves

// Per-block partials + completion counter. g_done is statically zero and is
// reset by the last block each launch, so graph replays start clean.
__device__ float g_part[NBLK];
__device__ unsigned int g_done = 0;

__device__ __forceinline__ int vdist(unsigned int m, int p)
{
    const unsigned int down = m >> p;
    const unsigned int up   = m << (31 - p);
    const int dd = down ? (__ffs((int)down) - 1) : 63;
    const int du = up   ? __clz((int)up)         : 63;
    return min(dd, du);
}

__global__ void __launch_bounds__(256)
boundary_loss_kernel(const float* __restrict__ pred,
                     const float* __restrict__ targ,
                     float* __restrict__ out)
{
    const int tile = blockIdx.x;             // 0 .. 255
    const int b    = tile >> 5;              // 32 row-tiles per image
    const int h0   = (tile & 31) * TRB;      // first output row of this tile
    const int w    = threadIdx.x;            // column (one per thread)

    __shared__ unsigned int sh[TRB][GW];     // packed (d2_to_bg | d2_to_fg<<16)
    __shared__ float lutW[34];
    __shared__ float ws[8];
    __shared__ int   s_last;

    const int base = b * (Hn * Wn);
    const float*        pimg = pred + base;
    const unsigned int* timg = (const unsigned int*)(targ + base);

    // ---- front-batch ALL global loads (24 outstanding, clamped rows) ----
    const int start = h0 - R;
    unsigned int tw[NROWS];
    #pragma unroll
    for (int k = 0; k < NROWS; ++k) {
        const int hh = min(max(start + k, 0), Hn - 1);
        tw[k] = __ldg(&timg[hh * Wn + w]);
    }
    float xr[TRB];
    #pragma unroll
    for (int r = 0; r < TRB; ++r)
        xr[r] = __ldg(&pimg[(h0 + r) * Wn + w]);

    // ---- LUT + pads while loads are in flight ----
    if (w < 34) {
        const float d = (w == 33) ? 64.0f : sqrtf((float)w);
        lutW[w] = 1.0f / (1.0f + __expf((d - 3.0f) * 0.2f));
    }
    if (w < 8 * TRB) {                       // 64 pad writes: 8 per row
        const int r = w >> 3, i = w & 7;
        const int idx = (i < R) ? i : (Wn + i);   // 0..3 / 260..263
        sh[r][idx] = PADV;
    }

    // ---- validity mask + class bitmask (bit 23 of 0.0f/1.0f IS the class) --
    unsigned int vm = (1u << NROWS) - 1u;
    if (start < 0)          vm &= ~((1u << (-start)) - 1u);
    if (start + NROWS > Hn) vm &=  (1u << (Hn - start)) - 1u;

    unsigned int fgm = 0u;
    #pragma unroll
    for (int k = 0; k < NROWS; ++k)
        fgm |= ((tw[k] >> 23) & 1u) << k;
    fgm &= vm;
    const unsigned int bgm = ~fgm & vm;

    // ---- vertical pass: packed d2 for both classes, 8 rows ----
    #pragma unroll
    for (int r = 0; r < TRB; ++r) {
        const int p  = r + R;
        const int dp = vdist(bgm, p);
        const int dn = vdist(fgm, p);
        sh[r][w + R] = (unsigned)(dp * dp) | ((unsigned)(dn * dn) << 16);
    }
    __syncthreads();

    // ---- horizontal 9-tap packed envelope + fused BCE * LUT weight ----
    float acc = 0.0f;
    #pragma unroll
    for (int r = 0; r < TRB; ++r) {
        unsigned int best = 0xFFFFFFFFu;
        #pragma unroll
        for (int k = 0; k < 9; ++k) {
            const int kk = k - R;
            const unsigned int add = (unsigned)(kk * kk) * 0x00010001u;
            best = __vminu2(best, sh[r][w + k] + add);
        }

        const bool fg = (fgm >> (r + R)) & 1u;
        const unsigned int d2 = fg ? (best & 0xFFFFu) : (best >> 16);
        const float weight = lutW[min(d2, 33u)];

        const float x   = xr[r];
        const float bce = fmaxf(x, 0.0f) - (fg ? x : 0.0f)
                        + __logf(1.0f + __expf(-fabsf(x)));
        acc = fmaf(bce, weight, acc);
    }

    // ---- block reduction (8 warps) ----
    #pragma unroll
    for (int off = 16; off > 0; off >>= 1)
        acc += __shfl_xor_sync(0xffffffffu, acc, off);
    if ((w & 31) == 0) ws[w >> 5] = acc;
    __syncthreads();

    // ---- publish per-block partial (contention-free STG), then count ----
    if (w == 0) {
        float s = 0.0f;
        #pragma unroll
        for (int i = 0; i < 8; ++i) s += ws[i];
        g_part[tile] = s;
        __threadfence();
        const unsigned int done = atomicAdd(&g_done, 1u);
        s_last = (done == (unsigned int)(NBLK - 1));
    }
    __syncthreads();

    // ---- last block: reduce the 256 partials and finalize ----
    if (s_last) {
        __threadfence();                     // acquire partials
        float s = g_part[w];                 // 256 threads, 256 partials
        #pragma unroll
        for (int off = 16; off > 0; off >>= 1)
            s += __shfl_xor_sync(0xffffffffu, s, off);
        if ((w & 31) == 0) ws[w >> 5] = s;
        __syncthreads();
        if (w == 0) {
            float tot = 0.0f;
            #pragma unroll
            for (int i = 0; i < 8; ++i) tot += ws[i];
            out[0] = tot * (1.0f / (float)(Bn * Hn * Wn));
            g_done = 0u;                     // reset for next launch / replay
        }
    }
}

extern "C" void kernel_launch(void* const* d_in, const int* in_sizes, int n_in,
                              void* d_out, int out_size)
{
    const float* pred = (const float*)d_in[0];
    const float* targ = (const float*)d_in[1];
    float* out = (float*)d_out;

    boundary_loss_kernel<<<NBLK, 256>>>(pred, targ, out);
}

// round 8
// speedup vs baseline: 1.2214x; 1.0037x over previous
#include <cuda_runtime.h>
#include <math.h>

#define Bn 8
#define Hn 256
#define Wn 256
#define R  4
#define TRB 16                    // output rows per block
#define NROWS (TRB + 2*R)         // 24 halo rows (fits uint32 mask)
#define GW (Wn + 2*R)             // 264 padded columns (idx = col + R)
#define NBLK (Bn * (Hn / TRB))    // 128 blocks
#define PADV 0x0FFF0FFFu          // "far" in both packed halves

// Per-block partials + completion counter. g_done is statically zero and is
// reset by the last block each launch, so graph replays start clean.
__device__ float g_part[NBLK];
__device__ unsigned int g_done = 0;

__device__ __forceinline__ int vdist(unsigned int m, int p)
{
    const unsigned int down = m >> p;
    const unsigned int up   = m << (31 - p);
    const int dd = down ? (__ffs((int)down) - 1) : 63;
    const int du = up   ? __clz((int)up)         : 63;
    return min(dd, du);
}

__global__ void __launch_bounds__(256)
boundary_loss_kernel(const float* __restrict__ pred,
                     const float* __restrict__ targ,
                     float* __restrict__ out)
{
    const int tile = blockIdx.x;             // 0 .. 127
    const int b    = tile >> 4;              // 16 row-tiles per image
    const int h0   = (tile & 15) * TRB;      // first output row of this tile
    const int w    = threadIdx.x;            // column (one per thread)

    __shared__ unsigned int sh[TRB][GW];     // packed (d2_to_bg | d2_to_fg<<16)
    __shared__ float lutW[34];
    __shared__ float ws[8];
    __shared__ int   s_last;

    const int base = b * (Hn * Wn);
    const float*        pimg = pred + base;
    const unsigned int* timg = (const unsigned int*)(targ + base);

    // ---- front-batch ALL global loads (40 outstanding) ----
    float xr[TRB];
    #pragma unroll
    for (int r = 0; r < TRB; ++r)
        xr[r] = __ldg(&pimg[(h0 + r) * Wn + w]);

    const int start = h0 - R;
    unsigned int tw[NROWS];
    #pragma unroll
    for (int k = 0; k < NROWS; ++k) {
        const int hh = min(max(start + k, 0), Hn - 1);
        tw[k] = __ldg(&timg[hh * Wn + w]);
    }

    // ---- LUT + pads while loads are in flight ----
    if (w < 34) {
        const float d = (w == 33) ? 64.0f : sqrtf((float)w);
        lutW[w] = 1.0f / (1.0f + __expf((d - 3.0f) * 0.2f));
    }
    if (w < 8 * TRB) {                       // 128 pad writes: 8 per row
        const int r = w >> 3, i = w & 7;
        const int idx = (i < R) ? i : (Wn + i);   // 0..3 / 260..263
        sh[r][idx] = PADV;
    }

    // ---- validity mask + class bitmask (bit 23 of 0.0f/1.0f IS the class) --
    unsigned int vm = (1u << NROWS) - 1u;
    if (start < 0)          vm &= ~((1u << (-start)) - 1u);
    if (start + NROWS > Hn) vm &=  (1u << (Hn - start)) - 1u;

    unsigned int fgm = 0u;
    #pragma unroll
    for (int k = 0; k < NROWS; ++k)
        fgm |= ((tw[k] >> 23) & 1u) << k;
    fgm &= vm;
    const unsigned int bgm = ~fgm & vm;

    // ---- vertical pass: packed d2 for both classes, 16 rows ----
    #pragma unroll
    for (int r = 0; r < TRB; ++r) {
        const int p  = r + R;
        const int dp = vdist(bgm, p);
        const int dn = vdist(fgm, p);
        sh[r][w + R] = (unsigned)(dp * dp) | ((unsigned)(dn * dn) << 16);
    }
    __syncthreads();

    // ---- horizontal 9-tap packed envelope + fused BCE * LUT weight ----
    float acc = 0.0f;
    #pragma unroll
    for (int r = 0; r < TRB; ++r) {
        unsigned int best = 0xFFFFFFFFu;
        #pragma unroll
        for (int k = 0; k < 9; ++k) {
            const int kk = k - R;
            const unsigned int add = (unsigned)(kk * kk) * 0x00010001u;
            best = __vminu2(best, sh[r][w + k] + add);
        }

        const bool fg = (fgm >> (r + R)) & 1u;
        const unsigned int d2 = fg ? (best & 0xFFFFu) : (best >> 16);
        const float weight = lutW[min(d2, 33u)];

        const float x   = xr[r];
        const float bce = fmaxf(x, 0.0f) - (fg ? x : 0.0f)
                        + __logf(1.0f + __expf(-fabsf(x)));
        acc = fmaf(bce, weight, acc);
    }

    // ---- block reduction (8 warps) ----
    #pragma unroll
    for (int off = 16; off > 0; off >>= 1)
        acc += __shfl_xor_sync(0xffffffffu, acc, off);
    if ((w & 31) == 0) ws[w >> 5] = acc;
    __syncthreads();

    // ---- publish per-block partial (contention-free STG), then count ----
    if (w == 0) {
        float s = 0.0f;
        #pragma unroll
        for (int i = 0; i < 8; ++i) s += ws[i];
        g_part[tile] = s;
        __threadfence();
        const unsigned int done = atomicAdd(&g_done, 1u);
        s_last = (done == (unsigned int)(NBLK - 1));
    }
    __syncthreads();

    // ---- last block: reduce the 128 partials and finalize ----
    if (s_last) {
        __threadfence();                     // acquire partials
        float s = (w < NBLK) ? g_part[w] : 0.0f;
        #pragma unroll
        for (int off = 16; off > 0; off >>= 1)
            s += __shfl_xor_sync(0xffffffffu, s, off);
        if ((w & 31) == 0) ws[w >> 5] = s;
        __syncthreads();
        if (w == 0) {
            float tot = 0.0f;
            #pragma unroll
            for (int i = 0; i < 8; ++i) tot += ws[i];
            out[0] = tot * (1.0f / (float)(Bn * Hn * Wn));
            g_done = 0u;                     // reset for next launch / replay
        }
    }
}

extern "C" void kernel_launch(void* const* d_in, const int* in_sizes, int n_in,
                              void* d_out, int out_size)
{
    const float* pred = (const float*)d_in[0];
    const float* targ = (const float*)d_in[1];
    float* out = (float*)d_out;

    boundary_loss_kernel<<<NBLK, 256>>>(pred, targ, out);
}